// round 14
// baseline (speedup 1.0000x reference)
#include <cuda_runtime.h>
#include <cstdint>

#define NL 16
#define NE 10
#define NC 128
#define NB_TOT 8192
#define NBASIS 968          // 16 linear + 136 pairs + 816 triples = 121 chunks of 8
#define EPAD 16             // e padded to 16 (two n8 mma tiles)
#define TPB 128             // 4 warps
#define BROWS_PER_CTA 512   // 4 warps x 4 tile-iters x 32 rows
#define PHS 12              // phi smem row stride (floats) -> conflict-free A-frag LDS

#define SMEM_B_FLOATS (NBASIS * EPAD)            // 15488
#define SMEM_PHI_FLOATS (4 * 2 * 32 * PHS)       // 4 warps x 2 bufs x 32 rows x 12
#define SMEM_BYTES ((SMEM_B_FLOATS + SMEM_PHI_FLOATS) * 4)   // 61952+12288 = 74240

typedef unsigned int uint;

// Per-channel basis->element matrix, Horner/lex order, e-padded, tf32-rounded.
__device__ __align__(16) static float g_B[(size_t)NC * NBASIS * EPAD];

__device__ __forceinline__ int id3(int a, int b, int d) { return ((a*NL + b)*NL + d) * 23; }

__device__ __forceinline__ uint cvt_tf32(float f) {
    uint r; asm("cvt.rna.tf32.f32 %0, %1;" : "=r"(r) : "f"(f)); return r;
}

// ---------------------------------------------------------------------------
// build_B: one thread per (m, c). Decodes basis index m -> (type,p,q,i) in the
// SAME order the compute kernel's unrolled nest emits monomials:
//   for p { linear(p); for q>=p { pair(p,q); for i>=q { triple(p,q,i) } } }
// Symmetrizes U, contracts with W, stores tf32-rounded at [c][m][epad 16].
// ---------------------------------------------------------------------------
__global__ void build_B_kernel(const float* __restrict__ U1, const float* __restrict__ U2,
                               const float* __restrict__ U3, const float* __restrict__ W1,
                               const float* __restrict__ W2, const float* __restrict__ W3) {
    int t = blockIdx.x * blockDim.x + threadIdx.x;
    if (t >= NBASIS * NC) return;
    int m = t >> 7;
    int c = t & (NC - 1);

    int p = 0;
    for (;;) {
        int np = NL - p;
        int blk = 1 + np + np * (np + 1) / 2;
        if (m < blk) break;
        m -= blk; p++;
    }
    int type, q = 0, i = 0;
    if (m == 0) {
        type = 1;
    } else {
        m -= 1;
        q = p;
        for (;;) {
            int blk = 1 + (NL - q);
            if (m < blk) break;
            m -= blk; q++;
        }
        if (m == 0) type = 2;
        else { type = 3; i = q + (m - 1); }
    }

    float row[NE];
    if (type == 1) {
        float u = U1[p];
        #pragma unroll
        for (int e = 0; e < NE; e++) row[e] = u * W1[e*NC + c];
    } else if (type == 2) {
        float s[4];
        #pragma unroll
        for (int k = 0; k < 4; k++) {
            float v = U2[(p*NL + q)*4 + k];
            if (p != q) v += U2[(q*NL + p)*4 + k];
            s[k] = v;
        }
        #pragma unroll
        for (int e = 0; e < NE; e++) {
            float a = 0.f;
            #pragma unroll
            for (int k = 0; k < 4; k++) a += s[k] * W2[(e*4 + k)*NC + c];
            row[e] = a;
        }
    } else {
        float s[23];
        for (int k = 0; k < 23; k++) {
            float v = U3[id3(p,q,i) + k];
            if (p < q && q < i) {
                v += U3[id3(p,i,q)+k] + U3[id3(q,p,i)+k] + U3[id3(q,i,p)+k]
                   + U3[id3(i,p,q)+k] + U3[id3(i,q,p)+k];
            } else if (p == q && q < i) {
                v += U3[id3(p,i,p)+k] + U3[id3(i,p,p)+k];
            } else if (p < q && q == i) {
                v += U3[id3(q,p,q)+k] + U3[id3(q,q,p)+k];
            }
            s[k] = v;
        }
        for (int e = 0; e < NE; e++) {
            float a = 0.f;
            for (int k = 0; k < 23; k++) a += s[k] * W3[(e*23 + k)*NC + c];
            row[e] = a;
        }
    }

    int mrow = t >> 7;
    float* dst = g_B + ((size_t)c * NBASIS + mrow) * EPAD;
    #pragma unroll
    for (int e = 0; e < NE; e++) dst[e] = __uint_as_float(cvt_tf32(row[e]));
    #pragma unroll
    for (int e = NE; e < EPAD; e++) dst[e] = 0.f;
}

// ---------------------------------------------------------------------------
// mma.sync m16n8k8 tf32, row.col, fp32 accumulate (D = A*B + D in place).
// ---------------------------------------------------------------------------
__device__ __forceinline__ void mma_tf32(float d[4], uint a0, uint a1, uint a2, uint a3,
                                         uint b0, uint b1) {
    asm volatile(
        "mma.sync.aligned.m16n8k8.row.col.f32.tf32.tf32.f32 "
        "{%0,%1,%2,%3}, {%4,%5,%6,%7}, {%8,%9}, {%0,%1,%2,%3};"
        : "+f"(d[0]), "+f"(d[1]), "+f"(d[2]), "+f"(d[3])
        : "r"(a0), "r"(a1), "r"(a2), "r"(a3), "r"(b0), "r"(b1));
}

// Flush one k8 chunk: cvt phi->tf32, store to this warp's phi buffer, load
// A fragments (rows 0-31 over two m16 A-tiles) and B fragments, 4 mmas.
// mm is a compile-time constant after full unroll (buffer parity folds).
__device__ __forceinline__ void flush_chunk(int mm, const float* ph, float* phw,
                                            const float* sB, int lane,
                                            float acc[2][2][4]) {
    const int buf = (mm >> 3) & 1;
    const int m0  = mm - 7;
    float* pb = phw + buf * (32 * PHS);

    uint pr[8];
    #pragma unroll
    for (int j = 0; j < 8; j++) pr[j] = cvt_tf32(ph[j]);
    uint4* dst = reinterpret_cast<uint4*>(pb + lane * PHS);
    dst[0] = make_uint4(pr[0], pr[1], pr[2], pr[3]);
    dst[1] = make_uint4(pr[4], pr[5], pr[6], pr[7]);
    __syncwarp();

    const int l4 = lane >> 2, lm = lane & 3;
    const uint* pu = reinterpret_cast<const uint*>(pb);
    const uint* bu = reinterpret_cast<const uint*>(sB);

    // B fragments (shared across both A-tiles)
    uint bf[2][2];
    #pragma unroll
    for (int nt = 0; nt < 2; nt++) {
        bf[nt][0] = bu[(m0 + lm)     * EPAD + nt*8 + l4];
        bf[nt][1] = bu[(m0 + 4 + lm) * EPAD + nt*8 + l4];
    }
    #pragma unroll
    for (int at = 0; at < 2; at++) {
        uint a0 = pu[(l4     + at*16) * PHS + lm];
        uint a1 = pu[(l4 + 8 + at*16) * PHS + lm];
        uint a2 = pu[(l4     + at*16) * PHS + lm + 4];
        uint a3 = pu[(l4 + 8 + at*16) * PHS + lm + 4];
        #pragma unroll
        for (int nt = 0; nt < 2; nt++)
            mma_tf32(acc[at][nt], a0, a1, a2, a3, bf[nt][0], bf[nt][1]);
    }
    __syncwarp();
}

// ---------------------------------------------------------------------------
// Main kernel. CTA = (channel c, 512 b-rows). Each warp: 4 tiles of 32 rows.
// Per tile: lane owns one b-row, x[16] in registers; the fully-unrolled
// monomial nest emits phi with static indices and flushes every 8th into a
// k8 mma chunk. 121 chunks. Epilogue contracts Z with y via shfl reduction.
// ---------------------------------------------------------------------------
__global__ __launch_bounds__(TPB)
void contract_mma_kernel(const float* __restrict__ x, const float* __restrict__ y,
                         float* __restrict__ out) {
    extern __shared__ __align__(16) float smem[];
    float* sB  = smem;                                  // [NBASIS][EPAD]
    const int tid  = threadIdx.x;
    const int warp = tid >> 5;
    const int lane = tid & 31;
    const int c    = blockIdx.y;
    float* phw = smem + SMEM_B_FLOATS + warp * (2 * 32 * PHS);

    // Stage B = M[c] (tf32 bits) into shared once.
    {
        const float4* src = reinterpret_cast<const float4*>(g_B + (size_t)c * NBASIS * EPAD);
        float4* dst = reinterpret_cast<float4*>(sB);
        for (int j = tid; j < SMEM_B_FLOATS / 4; j += TPB) dst[j] = src[j];
    }
    __syncthreads();

    for (int t4 = 0; t4 < 4; t4++) {
        const int bb = blockIdx.x * BROWS_PER_CTA + t4 * 128 + warp * 32;

        // Lane's own x row in registers.
        float xr[NL];
        {
            const float4* xp = reinterpret_cast<const float4*>(
                x + ((size_t)(bb + lane) * NC + c) * NL);
            #pragma unroll
            for (int j = 0; j < 4; j++) {
                float4 v = xp[j];
                xr[4*j+0] = v.x; xr[4*j+1] = v.y; xr[4*j+2] = v.z; xr[4*j+3] = v.w;
            }
        }

        float acc[2][2][4];
        #pragma unroll
        for (int a = 0; a < 2; a++)
            #pragma unroll
            for (int n = 0; n < 2; n++)
                #pragma unroll
                for (int k = 0; k < 4; k++) acc[a][n][k] = 0.f;

        float ph[8];
        int mm = 0;
        #pragma unroll
        for (int p = 0; p < NL; p++) {
            ph[mm & 7] = xr[p];
            if ((mm & 7) == 7) flush_chunk(mm, ph, phw, sB, lane, acc);
            mm++;
            #pragma unroll
            for (int q = p; q < NL; q++) {
                float pq = xr[p] * xr[q];
                ph[mm & 7] = pq;
                if ((mm & 7) == 7) flush_chunk(mm, ph, phw, sB, lane, acc);
                mm++;
                #pragma unroll
                for (int i = q; i < NL; i++) {
                    ph[mm & 7] = pq * xr[i];
                    if ((mm & 7) == 7) flush_chunk(mm, ph, phw, sB, lane, acc);
                    mm++;
                }
            }
        }
        // mm == 968 here; 121 chunks flushed.

        // Epilogue: out[b,c] = sum_e y[b,e] * Z[b,e]
        const int t = lane & 3, g = lane >> 2;
        #pragma unroll
        for (int at = 0; at < 2; at++) {
            const int rA = bb + at*16 + g;
            const int rB = rA + 8;
            float pA = 0.f, pB = 0.f;
            #pragma unroll
            for (int nt = 0; nt < 2; nt++) {
                int e0 = nt*8 + 2*t, e1 = e0 + 1;
                float y0A = (e0 < NE) ? y[(size_t)rA*NE + e0] : 0.f;
                float y1A = (e1 < NE) ? y[(size_t)rA*NE + e1] : 0.f;
                float y0B = (e0 < NE) ? y[(size_t)rB*NE + e0] : 0.f;
                float y1B = (e1 < NE) ? y[(size_t)rB*NE + e1] : 0.f;
                pA += acc[at][nt][0]*y0A + acc[at][nt][1]*y1A;
                pB += acc[at][nt][2]*y0B + acc[at][nt][3]*y1B;
            }
            pA += __shfl_xor_sync(0xFFFFFFFFu, pA, 1);
            pA += __shfl_xor_sync(0xFFFFFFFFu, pA, 2);
            pB += __shfl_xor_sync(0xFFFFFFFFu, pB, 1);
            pB += __shfl_xor_sync(0xFFFFFFFFu, pB, 2);
            if (t == 0) {
                out[(size_t)rA * NC + c] = pA;
                out[(size_t)rB * NC + c] = pB;
            }
        }
    }
}

// ---------------------------------------------------------------------------
extern "C" void kernel_launch(void* const* d_in, const int* in_sizes, int n_in,
                              void* d_out, int out_size) {
    const float *x = 0, *y = 0, *U1 = 0, *U2 = 0, *U3 = 0, *W1 = 0, *W2 = 0, *W3 = 0;
    for (int i = 0; i < n_in; i++) {
        const float* p = (const float*)d_in[i];
        switch (in_sizes[i]) {
            case 8192 * 128 * 16:   x  = p; break;   // (B,C,L)
            case 8192 * 10:         y  = p; break;   // (B,E)
            case 16:                U1 = p; break;   // (L,K1)
            case 16 * 16 * 4:       U2 = p; break;   // (L,L,K2)
            case 16 * 16 * 16 * 23: U3 = p; break;   // (L,L,L,K3)
            case 10 * 1 * 128:      W1 = p; break;   // (E,K1,C)
            case 10 * 4 * 128:      W2 = p; break;   // (E,K2,C)
            case 10 * 23 * 128:     W3 = p; break;   // (E,K3,C)
        }
    }

    cudaFuncSetAttribute(contract_mma_kernel,
                         cudaFuncAttributeMaxDynamicSharedMemorySize, SMEM_BYTES);

    const int tot = NBASIS * NC;
    build_B_kernel<<<(tot + 255) / 256, 256>>>(U1, U2, U3, W1, W2, W3);

    dim3 grid(NB_TOT / BROWS_PER_CTA, NC);   // (16, 128)
    contract_mma_kernel<<<grid, TPB, SMEM_BYTES>>>(x, y, (float*)d_out);
}

// round 17
// speedup vs baseline: 8.0391x; 8.0391x over previous
#include <cuda_runtime.h>
#include <cstdint>

#define NL 16
#define NE 10
#define NC 128
#define NB_TOT 8192
#define NBASIS 968          // 16 linear + 136 pairs + 816 triples
#define NCHUNK 121          // k8 chunks (968/8)
#define TPB 128             // 4 warps
#define BROWS_PER_CTA 512   // 4 warps x 4 t4-iters x 32 rows
#define PHS 68              // phi smem row stride (words): conflict-free STS/LDS

#define BF_WORDS_PER_C (NCHUNK * 2 * 32 * 2)             // 15488 (61952 B)
#define ABUF_WORDS (32 * PHS)                            // 2176 per warp
#define SMEM_BYTES ((BF_WORDS_PER_C + 4 * ABUF_WORDS) * 4)   // 61952+34816 = 96768

typedef unsigned int uint;

// Per-channel B matrix pre-packed in m16n8k8 fragment order, tf32-rounded:
// g_Bf[c][ch][nt][lane] = float2( B[8ch+lm][8nt+l4], B[8ch+4+lm][8nt+l4] ),
// lane = l4*4+lm in [0,32). 128 * 121 * 2 * 32 float2 = 7.9 MB.
__device__ __align__(16) static float g_Bf[(size_t)NC * BF_WORDS_PER_C];

__device__ __forceinline__ int id3(int a, int b, int d) { return ((a*NL + b)*NL + d) * 23; }

__device__ __forceinline__ uint cvt_tf32(float f) {
    uint r; asm("cvt.rna.tf32.f32 %0, %1;" : "=r"(r) : "f"(f)); return r;
}

// ---------------------------------------------------------------------------
// build_B: one thread per (m, c). Decodes basis index m -> (type,p,q,i) in the
// SAME order the compute kernel's nest emits monomials, symmetrizes U,
// contracts with W, scatters tf32-rounded values into fragment layout.
// ---------------------------------------------------------------------------
__global__ void build_B_kernel(const float* __restrict__ U1, const float* __restrict__ U2,
                               const float* __restrict__ U3, const float* __restrict__ W1,
                               const float* __restrict__ W2, const float* __restrict__ W3) {
    int t = blockIdx.x * blockDim.x + threadIdx.x;
    if (t >= NBASIS * NC) return;
    int m = t >> 7;
    int c = t & (NC - 1);
    const int m_keep = m;

    int p = 0;
    for (;;) {
        int np = NL - p;
        int blk = 1 + np + np * (np + 1) / 2;
        if (m < blk) break;
        m -= blk; p++;
    }
    int type, q = 0, i = 0;
    if (m == 0) {
        type = 1;
    } else {
        m -= 1;
        q = p;
        for (;;) {
            int blk = 1 + (NL - q);
            if (m < blk) break;
            m -= blk; q++;
        }
        if (m == 0) type = 2;
        else { type = 3; i = q + (m - 1); }
    }

    float row[NE];
    if (type == 1) {
        float u = U1[p];
        #pragma unroll
        for (int e = 0; e < NE; e++) row[e] = u * W1[e*NC + c];
    } else if (type == 2) {
        float s[4];
        #pragma unroll
        for (int k = 0; k < 4; k++) {
            float v = U2[(p*NL + q)*4 + k];
            if (p != q) v += U2[(q*NL + p)*4 + k];
            s[k] = v;
        }
        #pragma unroll
        for (int e = 0; e < NE; e++) {
            float a = 0.f;
            #pragma unroll
            for (int k = 0; k < 4; k++) a += s[k] * W2[(e*4 + k)*NC + c];
            row[e] = a;
        }
    } else {
        float s[23];
        for (int k = 0; k < 23; k++) {
            float v = U3[id3(p,q,i) + k];
            if (p < q && q < i) {
                v += U3[id3(p,i,q)+k] + U3[id3(q,p,i)+k] + U3[id3(q,i,p)+k]
                   + U3[id3(i,p,q)+k] + U3[id3(i,q,p)+k];
            } else if (p == q && q < i) {
                v += U3[id3(p,i,p)+k] + U3[id3(i,p,p)+k];
            } else if (p < q && q == i) {
                v += U3[id3(q,p,q)+k] + U3[id3(q,q,p)+k];
            }
            s[k] = v;
        }
        for (int e = 0; e < NE; e++) {
            float a = 0.f;
            for (int k = 0; k < 23; k++) a += s[k] * W3[(e*23 + k)*NC + c];
            row[e] = a;
        }
    }

    // Scatter into fragment layout (16 e-slots, zeros for e >= 10).
    // 32 lanes per (chunk, nt) tile; float2 per lane (k-halves).
    const int ch    = m_keep >> 3;
    const int kk    = m_keep & 7;
    const int khalf = kk >> 2;
    const int lmm   = kk & 3;
    #pragma unroll
    for (int e = 0; e < 16; e++) {
        float v = (e < NE) ? row[e] : 0.f;
        int lane = (e & 7) * 4 + lmm;
        int nt   = e >> 3;
        size_t idx = ((((size_t)c * NCHUNK + ch) * 2 + nt) * 32 + lane) * 2 + khalf;
        g_Bf[idx] = __uint_as_float(cvt_tf32(v));
    }
}

// ---------------------------------------------------------------------------
// mma.sync m16n8k8 tf32, row.col, fp32 accumulate in place.
// ---------------------------------------------------------------------------
__device__ __forceinline__ void mma_tf32(float d[4], uint a0, uint a1, uint a2, uint a3,
                                         uint b0, uint b1) {
    asm volatile(
        "mma.sync.aligned.m16n8k8.row.col.f32.tf32.tf32.f32 "
        "{%0,%1,%2,%3}, {%4,%5,%6,%7}, {%8,%9}, {%0,%1,%2,%3};"
        : "+f"(d[0]), "+f"(d[1]), "+f"(d[2]), "+f"(d[3])
        : "r"(a0), "r"(a1), "r"(a2), "r"(a3), "r"(b0), "r"(b1));
}

// Consume n k8-subchunks from the warp's 64-monomial phi buffer.
// f = flush index (chunk base = 8f). Runtime loop keeps code small.
__device__ __forceinline__ void flushN(const uint* __restrict__ abW,
                                       const float* __restrict__ sBf,
                                       int f, int n, int l4, int lm, int lane,
                                       float acc[2][2][4]) {
    __syncwarp();
    #pragma unroll 1
    for (int s = 0; s < n; s++) {
        const int k0  = s * 8;
        const int chB = f * 8 + s;
        const float2 bv0 = *reinterpret_cast<const float2*>(sBf + ((size_t)(chB*2 + 0)*32 + lane)*2);
        const float2 bv1 = *reinterpret_cast<const float2*>(sBf + ((size_t)(chB*2 + 1)*32 + lane)*2);
        const uint b00 = __float_as_uint(bv0.x), b01 = __float_as_uint(bv0.y);
        const uint b10 = __float_as_uint(bv1.x), b11 = __float_as_uint(bv1.y);
        #pragma unroll
        for (int at = 0; at < 2; at++) {
            uint a0 = abW[(l4      + at*16) * PHS + k0 + lm];
            uint a1 = abW[(l4 + 8  + at*16) * PHS + k0 + lm];
            uint a2 = abW[(l4      + at*16) * PHS + k0 + lm + 4];
            uint a3 = abW[(l4 + 8  + at*16) * PHS + k0 + lm + 4];
            mma_tf32(acc[at][0], a0, a1, a2, a3, b00, b01);
            mma_tf32(acc[at][1], a0, a1, a2, a3, b10, b11);
        }
    }
    __syncwarp();
}

// ---------------------------------------------------------------------------
// Main kernel. CTA = (channel c, 512 b-rows); warp-tile = 32 rows; t4 runtime
// loop (code shared across iterations -> warm I$). Lane owns one b-row; the
// static monomial nest emits phi with compile-time indices, packs 4 per
// STS.128 into the warp's 64-wide buffer (stride 68: conflict-free), and
// every 64 monomials flushes 8 k8 mma subchunks. B read as packed fragments.
// ---------------------------------------------------------------------------
__global__ __launch_bounds__(TPB)
void contract_mma_kernel(const float* __restrict__ x, const float* __restrict__ y,
                         float* __restrict__ out) {
    extern __shared__ __align__(16) float smem[];
    float* sBf = smem;                                   // packed B fragments
    const int tid  = threadIdx.x;
    const int warp = tid >> 5;
    const int lane = tid & 31;
    const int l4   = lane >> 2;
    const int lm   = lane & 3;
    const int c    = blockIdx.y;
    uint* abW = reinterpret_cast<uint*>(smem + BF_WORDS_PER_C) + warp * ABUF_WORDS;

    // Stage packed B for this channel.
    {
        const float4* src = reinterpret_cast<const float4*>(g_Bf + (size_t)c * BF_WORDS_PER_C);
        float4* dst = reinterpret_cast<float4*>(sBf);
        for (int j = tid; j < BF_WORDS_PER_C / 4; j += TPB) dst[j] = src[j];
    }
    __syncthreads();

    #pragma unroll 1
    for (int t4 = 0; t4 < 4; t4++) {
        const int bb = blockIdx.x * BROWS_PER_CTA + t4 * 128 + warp * 32;

        float xr[NL];
        {
            const float4* xp = reinterpret_cast<const float4*>(
                x + ((size_t)(bb + lane) * NC + c) * NL);
            #pragma unroll
            for (int j = 0; j < 4; j++) {
                float4 v = xp[j];
                xr[4*j+0] = v.x; xr[4*j+1] = v.y; xr[4*j+2] = v.z; xr[4*j+3] = v.w;
            }
        }

        float acc[2][2][4];
        #pragma unroll
        for (int a = 0; a < 2; a++)
            #pragma unroll
            for (int n = 0; n < 2; n++)
                #pragma unroll
                for (int k = 0; k < 4; k++) acc[a][n][k] = 0.f;

        uint pr[4];
        int m = 0;

#define EMIT(VAL) do {                                                         \
        pr[m & 3] = cvt_tf32(VAL);                                             \
        if ((m & 3) == 3) {                                                    \
            uint4* d4 = reinterpret_cast<uint4*>(abW + lane*PHS + (m & 63) - 3); \
            *d4 = make_uint4(pr[0], pr[1], pr[2], pr[3]);                      \
        }                                                                      \
        if ((m & 63) == 63) flushN(abW, sBf, (m >> 6), 8, l4, lm, lane, acc);  \
        m++;                                                                   \
    } while (0)

        #pragma unroll
        for (int p = 0; p < NL; p++) {
            EMIT(xr[p]);
            #pragma unroll
            for (int q = p; q < NL; q++) {
                float pq = xr[p] * xr[q];
                EMIT(pq);
                #pragma unroll
                for (int i = q; i < NL; i++) {
                    EMIT(pq * xr[i]);
                }
            }
        }
#undef EMIT
        // m == 968: monomials 960..967 sit in buffer words 0..7 -> one subchunk.
        flushN(abW, sBf, 15, 1, l4, lm, lane, acc);

        // Epilogue: out[b,c] = sum_e y[b,e] * Z[b,e] (fragment layout of D).
        const int t = lane & 3, g = lane >> 2;
        #pragma unroll
        for (int at = 0; at < 2; at++) {
            const int rA = bb + at*16 + g;
            const int rB = rA + 8;
            float pA = 0.f, pB = 0.f;
            #pragma unroll
            for (int nt = 0; nt < 2; nt++) {
                int e0 = nt*8 + 2*t, e1 = e0 + 1;
                float y0A = (e0 < NE) ? y[(size_t)rA*NE + e0] : 0.f;
                float y1A = (e1 < NE) ? y[(size_t)rA*NE + e1] : 0.f;
                float y0B = (e0 < NE) ? y[(size_t)rB*NE + e0] : 0.f;
                float y1B = (e1 < NE) ? y[(size_t)rB*NE + e1] : 0.f;
                pA += acc[at][nt][0]*y0A + acc[at][nt][1]*y1A;
                pB += acc[at][nt][2]*y0B + acc[at][nt][3]*y1B;
            }
            pA += __shfl_xor_sync(0xFFFFFFFFu, pA, 1);
            pA += __shfl_xor_sync(0xFFFFFFFFu, pA, 2);
            pB += __shfl_xor_sync(0xFFFFFFFFu, pB, 1);
            pB += __shfl_xor_sync(0xFFFFFFFFu, pB, 2);
            if (t == 0) {
                out[(size_t)rA * NC + c] = pA;
                out[(size_t)rB * NC + c] = pB;
            }
        }
    }
}

// ---------------------------------------------------------------------------
extern "C" void kernel_launch(void* const* d_in, const int* in_sizes, int n_in,
                              void* d_out, int out_size) {
    const float *x = 0, *y = 0, *U1 = 0, *U2 = 0, *U3 = 0, *W1 = 0, *W2 = 0, *W3 = 0;
    for (int i = 0; i < n_in; i++) {
        const float* p = (const float*)d_in[i];
        switch (in_sizes[i]) {
            case 8192 * 128 * 16:   x  = p; break;   // (B,C,L)
            case 8192 * 10:         y  = p; break;   // (B,E)
            case 16:                U1 = p; break;   // (L,K1)
            case 16 * 16 * 4:       U2 = p; break;   // (L,L,K2)
            case 16 * 16 * 16 * 23: U3 = p; break;   // (L,L,L,K3)
            case 10 * 1 * 128:      W1 = p; break;   // (E,K1,C)
            case 10 * 4 * 128:      W2 = p; break;   // (E,K2,C)
            case 10 * 23 * 128:     W3 = p; break;   // (E,K3,C)
        }
    }

    cudaFuncSetAttribute(contract_mma_kernel,
                         cudaFuncAttributeMaxDynamicSharedMemorySize, SMEM_BYTES);

    const int tot = NBASIS * NC;
    build_B_kernel<<<(tot + 255) / 256, 256>>>(U1, U2, U3, W1, W2, W3);

    dim3 grid(NB_TOT / BROWS_PER_CTA, NC);   // (16, 128)
    contract_mma_kernel<<<grid, TPB, SMEM_BYTES>>>(x, y, (float*)d_out);
}